// round 2
// baseline (speedup 1.0000x reference)
#include <cuda_runtime.h>
#include <math.h>

#define N_NODES 50000
#define DIM     200
#define N_RELS  500
#define NHID    100
#define NHEADS  2
#define E_BASE  150000
#define E_NHOP  30000
#define E_ALL   180000

// ---------------- scratch (static device globals; no allocs) ----------------
__device__ float g_x[N_NODES * DIM];            // l2-normalized entities
__device__ float g_Bcat1[400 * DIM];            // [h0dst;h0src;h1dst;h1src] rows
__device__ float g_relproj1[NHEADS * N_RELS * NHID];
__device__ float g_proj1[N_NODES * 400];
__device__ int   g_dst[E_ALL];
__device__ int   g_src[E_ALL];
__device__ int   g_rA[E_ALL];
__device__ int   g_rB[E_ALL];
__device__ float g_rowsum1[NHEADS * N_NODES];
__device__ float g_acc1[NHEADS * N_NODES * NHID];
__device__ float g_x1[N_NODES * DIM];
__device__ float g_outrel[N_RELS * DIM];
__device__ float g_Bcat2[400 * DIM];
__device__ float g_relproj2[N_RELS * DIM];
__device__ float g_proj2[N_NODES * 400];
__device__ float g_rowsum2[N_NODES];
__device__ float g_acc2[N_NODES * DIM];
__device__ float g_Wt[DIM * DIM];               // W_entities transposed
__device__ float g_entlin[N_NODES * DIM];
__device__ float g_mask[N_NODES];

// ---------------- small helpers ----------------
__device__ __forceinline__ float warp_sum(float v) {
    #pragma unroll
    for (int o = 16; o; o >>= 1) v += __shfl_xor_sync(0xFFFFFFFFu, v, o);
    return v;
}

// ---------------- zero accumulators ----------------
__global__ void zero_all() {
    int stride = gridDim.x * blockDim.x;
    for (int i = blockIdx.x * blockDim.x + threadIdx.x;
         i < NHEADS * N_NODES * NHID; i += stride) {
        g_acc1[i] = 0.f;
        if (i < N_NODES * DIM) g_acc2[i] = 0.f;
        if (i < NHEADS * N_NODES) g_rowsum1[i] = 0.f;
        if (i < N_NODES) { g_rowsum2[i] = 0.f; g_mask[i] = 0.f; }
    }
}

// ---------------- build Bcat1/Bcat2/Wt + edge arrays ----------------
__global__ void prep(const float* __restrict__ a_heads,
                     const float* __restrict__ a_out,
                     const float* __restrict__ W_ent,
                     const int* __restrict__ edge_list,
                     const int* __restrict__ edge_type,
                     const int* __restrict__ nhop) {
    int i = blockIdx.x * blockDim.x + threadIdx.x;
    if (i < 400 * DIM) {
        int j = i / DIM, k = i % DIM;
        // Bcat1: rows 0-99 h0 dst, 100-199 h0 src, 200-299 h1 dst, 300-399 h1 src
        int h = j / 200, w = j % 200, sect = w / NHID, jr = w % NHID;
        g_Bcat1[i] = a_heads[(h * NHID + jr) * 600 + sect * DIM + k];
        // Bcat2: rows 0-199 = a_out[:,0:200] (dst), 200-399 = a_out[:,200:400] (src)
        g_Bcat2[i] = a_out[(j % 200) * 600 + (j / 200) * DIM + k];
        if (i < DIM * DIM) g_Wt[i] = W_ent[(i % DIM) * DIM + i / DIM];
    }
    if (i < E_ALL) {
        if (i < E_BASE) {
            g_dst[i] = edge_list[i];
            g_src[i] = edge_list[E_BASE + i];
            g_rA[i]  = edge_type[i];
            g_rB[i]  = -1;
        } else {
            int t = i - E_BASE;
            g_dst[i] = nhop[t * 4 + 3];
            g_src[i] = nhop[t * 4 + 0];
            g_rA[i]  = nhop[t * 4 + 1];
            g_rB[i]  = nhop[t * 4 + 2];
        }
    }
}

__global__ void mask_scatter(const int* __restrict__ batch, int n) {
    int i = blockIdx.x * blockDim.x + threadIdx.x;
    if (i < n) g_mask[batch[i]] = 1.0f;
}

// ---------------- row-wise l2 norm into g_x (no symbol passed from host) ----
__global__ void l2norm_entities(const float* __restrict__ in) {
    int w = (blockIdx.x * blockDim.x + threadIdx.x) >> 5;
    int lane = threadIdx.x & 31;
    if (w >= N_NODES) return;
    const float* r = in + (size_t)w * DIM;
    float ss = 0.f;
    for (int j = lane; j < DIM; j += 32) { float v = r[j]; ss += v * v; }
    ss = warp_sum(ss);
    float sc = 1.f / fmaxf(sqrtf(ss), 1e-12f);
    for (int j = lane; j < DIM; j += 32) g_x[(size_t)w * DIM + j] = r[j] * sc;
}

// ---------------- relation projections (small, naive) ----------------
__global__ void relproj1_k(const float* __restrict__ rel, const float* __restrict__ a_heads) {
    int i = blockIdx.x * blockDim.x + threadIdx.x;
    if (i >= NHEADS * N_RELS * NHID) return;
    int h = i / (N_RELS * NHID);
    int rem = i % (N_RELS * NHID);
    int r = rem / NHID, j = rem % NHID;
    const float* ar = a_heads + (h * NHID + j) * 600 + 400;
    const float* rr = rel + r * DIM;
    float s = 0.f;
    #pragma unroll 4
    for (int k = 0; k < DIM; k++) s += rr[k] * ar[k];
    g_relproj1[i] = s;
}

__global__ void outrel_k(const float* __restrict__ rel, const float* __restrict__ W_gat) {
    int i = blockIdx.x * blockDim.x + threadIdx.x;
    if (i >= N_RELS * DIM) return;
    int r = i / DIM, j = i % DIM;
    const float* rr = rel + r * DIM;
    float s = 0.f;
    #pragma unroll 4
    for (int k = 0; k < DIM; k++) s += rr[k] * W_gat[k * DIM + j];
    g_outrel[i] = s;
}

__global__ void relproj2_k(const float* __restrict__ a_out) {
    int i = blockIdx.x * blockDim.x + threadIdx.x;
    if (i >= N_RELS * DIM) return;
    int r = i / DIM, j = i % DIM;
    const float* rr = g_outrel + r * DIM;
    const float* ar = a_out + j * 600 + 400;
    float s = 0.f;
    #pragma unroll 4
    for (int k = 0; k < DIM; k++) s += rr[k] * ar[k];
    g_relproj2[i] = s;
}

// ---------------- tiled SGEMM: C[M,Nn] = A[M,K] * B[Nn,K]^T ----------------
// Buffers bound INSIDE device code via template selector — never pass a
// __device__ symbol from host (host-side decay gives the host shadow addr,
// which GB300 ATS happily lets kernels write: silent corruption).
#define BM 64
#define BN 64
#define BKK 8
template <int SEL>
__global__ void sgemm_nt_k() {
    const float* A; const float* B; float* C; int M, Nn, K;
    if (SEL == 0) { A = g_x;  B = g_Bcat1; C = g_proj1;  M = N_NODES; Nn = 400; K = DIM; }
    if (SEL == 1) { A = g_x1; B = g_Bcat2; C = g_proj2;  M = N_NODES; Nn = 400; K = DIM; }
    if (SEL == 2) { A = g_x;  B = g_Wt;    C = g_entlin; M = N_NODES; Nn = DIM; K = DIM; }
    __shared__ float As[BKK][BM];
    __shared__ float Bs[BKK][BN];
    int tid = threadIdx.x;
    int tx = tid % 16, ty = tid / 16;
    int row0 = blockIdx.y * BM;
    int col0 = blockIdx.x * BN;
    float acc[4][4] = {};
    for (int k0 = 0; k0 < K; k0 += BKK) {
        #pragma unroll
        for (int i = 0; i < 2; i++) {
            int idx = tid + i * 256;        // 0..511
            int m = idx / BKK, k = idx % BKK;
            int gr = row0 + m, gk = k0 + k;
            As[k][m] = (gr < M && gk < K) ? A[(size_t)gr * K + gk] : 0.f;
            int gc = col0 + m;
            Bs[k][m] = (gc < Nn && gk < K) ? B[(size_t)gc * K + gk] : 0.f;
        }
        __syncthreads();
        #pragma unroll
        for (int k = 0; k < BKK; k++) {
            float a[4], b[4];
            #pragma unroll
            for (int i = 0; i < 4; i++) a[i] = As[k][ty * 4 + i];
            #pragma unroll
            for (int j = 0; j < 4; j++) b[j] = Bs[k][tx * 4 + j];
            #pragma unroll
            for (int i = 0; i < 4; i++)
                #pragma unroll
                for (int j = 0; j < 4; j++)
                    acc[i][j] += a[i] * b[j];
        }
        __syncthreads();
    }
    #pragma unroll
    for (int i = 0; i < 4; i++) {
        int gr = row0 + ty * 4 + i;
        if (gr >= M) continue;
        #pragma unroll
        for (int j = 0; j < 4; j++) {
            int gc = col0 + tx * 4 + j;
            if (gc < Nn) C[(size_t)gr * Nn + gc] = acc[i][j];
        }
    }
}

// ---------------- edge pass, layer 1 (warp per edge, per head) ----------------
__global__ void edge_pass1(const float* __restrict__ a2_heads) {
    int gw = (blockIdx.x * blockDim.x + threadIdx.x) >> 5;
    int lane = threadIdx.x & 31;
    int h = blockIdx.y;
    if (gw >= E_ALL) return;
    int d = g_dst[gw], s = g_src[gw], ra = g_rA[gw], rb = g_rB[gw];
    const float* pd = g_proj1 + (size_t)d * 400 + h * 200;
    const float* ps = g_proj1 + (size_t)s * 400 + h * 200 + 100;
    const float* rp = g_relproj1 + (h * N_RELS + ra) * NHID;
    const float* rp2 = (rb >= 0) ? (g_relproj1 + (h * N_RELS + rb) * NHID) : nullptr;
    const float* a2 = a2_heads + h * NHID;
    float m[4];
    float dot = 0.f;
    #pragma unroll
    for (int t = 0; t < 4; t++) {
        int j = lane + 32 * t;
        float v = 0.f;
        if (j < NHID) {
            v = pd[j] + ps[j] + rp[j];
            if (rp2) v += rp2[j];
            dot += v * a2[j];
        }
        m[t] = v;
    }
    dot = warp_sum(dot);
    float lr = dot > 0.f ? dot : 0.2f * dot;
    float ev = expf(-lr);
    float* accrow = g_acc1 + ((size_t)h * N_NODES + d) * NHID;
    if (lane == 0) atomicAdd(&g_rowsum1[h * N_NODES + d], ev);
    #pragma unroll
    for (int t = 0; t < 4; t++) {
        int j = lane + 32 * t;
        if (j < NHID) atomicAdd(&accrow[j], ev * m[t]);
    }
}

// ---------------- combine layer-1 heads -> x1 (with elu) ----------------
__global__ void combine1() {
    int i = blockIdx.x * blockDim.x + threadIdx.x;
    if (i >= N_NODES * DIM) return;
    int n = i / DIM, c = i % DIM;
    int h = c / NHID, j = c % NHID;
    float rs = g_rowsum1[h * N_NODES + n];
    rs = (rs == 0.f) ? 1e-12f : rs;
    float v = g_acc1[((size_t)h * N_NODES + n) * NHID + j] / rs;
    g_x1[i] = v > 0.f ? v : (expf(v) - 1.f);
}

// ---------------- edge pass, layer 2 ----------------
__global__ void edge_pass2(const float* __restrict__ a2_out) {
    int gw = (blockIdx.x * blockDim.x + threadIdx.x) >> 5;
    int lane = threadIdx.x & 31;
    if (gw >= E_ALL) return;
    int d = g_dst[gw], s = g_src[gw], ra = g_rA[gw], rb = g_rB[gw];
    const float* pd = g_proj2 + (size_t)d * 400;
    const float* ps = g_proj2 + (size_t)s * 400 + 200;
    const float* rp = g_relproj2 + ra * DIM;
    const float* rp2 = (rb >= 0) ? (g_relproj2 + rb * DIM) : nullptr;
    float m[7];
    float dot = 0.f;
    #pragma unroll
    for (int t = 0; t < 7; t++) {
        int j = lane + 32 * t;
        float v = 0.f;
        if (j < DIM) {
            v = pd[j] + ps[j] + rp[j];
            if (rp2) v += rp2[j];
            dot += v * a2_out[j];
        }
        m[t] = v;
    }
    dot = warp_sum(dot);
    float lr = dot > 0.f ? dot : 0.2f * dot;
    float ev = expf(-lr);
    float* accrow = g_acc2 + (size_t)d * DIM;
    if (lane == 0) atomicAdd(&g_rowsum2[d], ev);
    #pragma unroll
    for (int t = 0; t < 7; t++) {
        int j = lane + 32 * t;
        if (j < DIM) atomicAdd(&accrow[j], ev * m[t]);
    }
}

// ---------------- finalize: out_ent = l2norm(entlin + mask*elu(acc2/rs)) ----
__global__ void finalize(float* __restrict__ out) {
    int n = (blockIdx.x * blockDim.x + threadIdx.x) >> 5;
    int lane = threadIdx.x & 31;
    if (n >= N_NODES) return;
    float rs = g_rowsum2[n];
    rs = (rs == 0.f) ? 1e-12f : rs;
    float mk = g_mask[n];
    float v[7];
    float ss = 0.f;
    #pragma unroll
    for (int t = 0; t < 7; t++) {
        int j = lane + 32 * t;
        float val = 0.f;
        if (j < DIM) {
            float hp = g_acc2[(size_t)n * DIM + j] / rs;
            float el = hp > 0.f ? hp : (expf(hp) - 1.f);
            val = g_entlin[(size_t)n * DIM + j] + mk * el;
            ss += val * val;
        }
        v[t] = val;
    }
    ss = warp_sum(ss);
    float sc = 1.f / fmaxf(sqrtf(ss), 1e-12f);
    #pragma unroll
    for (int t = 0; t < 7; t++) {
        int j = lane + 32 * t;
        if (j < DIM) out[(size_t)n * DIM + j] = v[t] * sc;
    }
}

__global__ void copy_tail(float* __restrict__ out) {
    int i = blockIdx.x * blockDim.x + threadIdx.x;
    const size_t base = (size_t)N_NODES * DIM;
    if (i < N_RELS * DIM) out[base + i] = g_outrel[i];
    if (i < N_NODES) out[base + N_RELS * DIM + i] = g_mask[i];
}

// ---------------- launch ----------------
extern "C" void kernel_launch(void* const* d_in, const int* in_sizes, int n_in,
                              void* d_out, int out_size) {
    const float* ent   = (const float*)d_in[0];
    const float* rel   = (const float*)d_in[1];
    const float* W_ent = (const float*)d_in[2];
    const float* W_gat = (const float*)d_in[3];
    const float* a_h   = (const float*)d_in[4];
    const float* a2_h  = (const float*)d_in[5];
    const float* a_o   = (const float*)d_in[6];
    const float* a2_o  = (const float*)d_in[7];
    const int*   batch = (const int*)d_in[8];
    const int*   elist = (const int*)d_in[9];
    const int*   etype = (const int*)d_in[10];
    const int*   nhop  = (const int*)d_in[11];
    float* out = (float*)d_out;
    int n_batch = in_sizes[8];

    zero_all<<<4096, 256>>>();
    prep<<<(E_ALL + 255) / 256, 256>>>(a_h, a_o, W_ent, elist, etype, nhop);
    mask_scatter<<<(n_batch + 255) / 256, 256>>>(batch, n_batch);
    l2norm_entities<<<(N_NODES * 32 + 255) / 256, 256>>>(ent);
    relproj1_k<<<(NHEADS * N_RELS * NHID + 255) / 256, 256>>>(rel, a_h);

    {
        dim3 grid((400 + BN - 1) / BN, (N_NODES + BM - 1) / BM);
        sgemm_nt_k<0><<<grid, 256>>>();
    }

    {
        dim3 grid((E_ALL + 7) / 8, NHEADS);
        edge_pass1<<<grid, 256>>>(a2_h);
    }
    combine1<<<(N_NODES * DIM + 255) / 256, 256>>>();

    outrel_k<<<(N_RELS * DIM + 255) / 256, 256>>>(rel, W_gat);
    relproj2_k<<<(N_RELS * DIM + 255) / 256, 256>>>(a_o);

    {
        dim3 grid((400 + BN - 1) / BN, (N_NODES + BM - 1) / BM);
        sgemm_nt_k<1><<<grid, 256>>>();
    }

    {
        dim3 grid((E_ALL + 7) / 8, 1);
        edge_pass2<<<grid, 256>>>(a2_o);
    }

    {
        dim3 grid((DIM + BN - 1) / BN, (N_NODES + BM - 1) / BM);
        sgemm_nt_k<2><<<grid, 256>>>();
    }

    finalize<<<(N_NODES * 32 + 255) / 256, 256>>>(out);
    copy_tail<<<(N_RELS * DIM + 255) / 256, 256>>>(out);
}

// round 3
// speedup vs baseline: 1.2932x; 1.2932x over previous
#include <cuda_runtime.h>
#include <math.h>

#define N_NODES 50000
#define DIM     200
#define N_RELS  500
#define NHID    100
#define NHEADS  2
#define E_BASE  150000
#define E_NHOP  30000
#define E_ALL   180000

// ---------------- scratch (static device globals; no allocs) ----------------
__device__ float g_x[N_NODES * DIM];            // l2-normalized entities
__device__ float g_BcatA[600 * DIM];            // rows 0-399: Bcat1, 400-599: W_ent^T
__device__ float g_relproj1[NHEADS * N_RELS * NHID];
__device__ float g_projA[N_NODES * 600];        // cols 0-399: proj1, 400-599: entlin
__device__ int   g_dst[E_ALL];
__device__ int   g_src[E_ALL];
__device__ int   g_rA[E_ALL];
__device__ int   g_rB[E_ALL];
__device__ float g_rowsum1[NHEADS * N_NODES];
__device__ float g_acc1[NHEADS * N_NODES * NHID];
__device__ float g_x1[N_NODES * DIM];
__device__ float g_outrel[N_RELS * DIM];
__device__ float g_Bcat2[400 * DIM];
__device__ float g_relproj2[N_RELS * DIM];
__device__ float g_proj2[N_NODES * 400];
__device__ float g_rowsum2[N_NODES];
__device__ float g_acc2[N_NODES * DIM];
__device__ float g_mask[N_NODES];

// ---------------- small helpers ----------------
__device__ __forceinline__ float warp_sum(float v) {
    #pragma unroll
    for (int o = 16; o; o >>= 1) v += __shfl_xor_sync(0xFFFFFFFFu, v, o);
    return v;
}

// ---------------- zero accumulators ----------------
__global__ void zero_all() {
    int stride = gridDim.x * blockDim.x;
    for (int i = blockIdx.x * blockDim.x + threadIdx.x;
         i < NHEADS * N_NODES * NHID; i += stride) {
        g_acc1[i] = 0.f;
        if (i < N_NODES * DIM) g_acc2[i] = 0.f;
        if (i < NHEADS * N_NODES) g_rowsum1[i] = 0.f;
        if (i < N_NODES) { g_rowsum2[i] = 0.f; g_mask[i] = 0.f; }
    }
}

// ---------------- build BcatA/Bcat2 + edge arrays ----------------
__global__ void prep(const float* __restrict__ a_heads,
                     const float* __restrict__ a_out,
                     const float* __restrict__ W_ent,
                     const int* __restrict__ edge_list,
                     const int* __restrict__ edge_type,
                     const int* __restrict__ nhop) {
    int i = blockIdx.x * blockDim.x + threadIdx.x;
    if (i < 600 * DIM) {
        int j = i / DIM, k = i % DIM;
        float v;
        if (j < 400) {
            // rows 0-99 h0 dst, 100-199 h0 src, 200-299 h1 dst, 300-399 h1 src
            int h = j / 200, w = j % 200, sect = w / NHID, jr = w % NHID;
            v = a_heads[(h * NHID + jr) * 600 + sect * DIM + k];
        } else {
            v = W_ent[k * DIM + (j - 400)];       // W_ent^T
        }
        g_BcatA[i] = v;
        if (i < 400 * DIM)
            g_Bcat2[i] = a_out[(j % 200) * 600 + (j / 200) * DIM + k];
    }
    if (i < E_ALL) {
        if (i < E_BASE) {
            g_dst[i] = edge_list[i];
            g_src[i] = edge_list[E_BASE + i];
            g_rA[i]  = edge_type[i];
            g_rB[i]  = -1;
        } else {
            int t = i - E_BASE;
            g_dst[i] = nhop[t * 4 + 3];
            g_src[i] = nhop[t * 4 + 0];
            g_rA[i]  = nhop[t * 4 + 1];
            g_rB[i]  = nhop[t * 4 + 2];
        }
    }
}

__global__ void mask_scatter(const int* __restrict__ batch, int n) {
    int i = blockIdx.x * blockDim.x + threadIdx.x;
    if (i < n) g_mask[batch[i]] = 1.0f;
}

// ---------------- row-wise l2 norm into g_x ----------------
__global__ void l2norm_entities(const float* __restrict__ in) {
    int w = (blockIdx.x * blockDim.x + threadIdx.x) >> 5;
    int lane = threadIdx.x & 31;
    if (w >= N_NODES) return;
    const float* r = in + (size_t)w * DIM;
    float ss = 0.f;
    for (int j = lane; j < DIM; j += 32) { float v = r[j]; ss += v * v; }
    ss = warp_sum(ss);
    float sc = 1.f / fmaxf(sqrtf(ss), 1e-12f);
    for (int j = lane; j < DIM; j += 32) g_x[(size_t)w * DIM + j] = r[j] * sc;
}

// ---------------- relation projections (small, naive) ----------------
__global__ void relproj1_k(const float* __restrict__ rel, const float* __restrict__ a_heads) {
    int i = blockIdx.x * blockDim.x + threadIdx.x;
    if (i >= NHEADS * N_RELS * NHID) return;
    int h = i / (N_RELS * NHID);
    int rem = i % (N_RELS * NHID);
    int r = rem / NHID, j = rem % NHID;
    const float* ar = a_heads + (h * NHID + j) * 600 + 400;
    const float* rr = rel + r * DIM;
    float s = 0.f;
    #pragma unroll 4
    for (int k = 0; k < DIM; k++) s += rr[k] * ar[k];
    g_relproj1[i] = s;
}

__global__ void outrel_k(const float* __restrict__ rel, const float* __restrict__ W_gat) {
    int i = blockIdx.x * blockDim.x + threadIdx.x;
    if (i >= N_RELS * DIM) return;
    int r = i / DIM, j = i % DIM;
    const float* rr = rel + r * DIM;
    float s = 0.f;
    #pragma unroll 4
    for (int k = 0; k < DIM; k++) s += rr[k] * W_gat[k * DIM + j];
    g_outrel[i] = s;
}

__global__ void relproj2_k(const float* __restrict__ a_out) {
    int i = blockIdx.x * blockDim.x + threadIdx.x;
    if (i >= N_RELS * DIM) return;
    int r = i / DIM, j = i % DIM;
    const float* rr = g_outrel + r * DIM;
    const float* ar = a_out + j * 600 + 400;
    float s = 0.f;
    #pragma unroll 4
    for (int k = 0; k < DIM; k++) s += rr[k] * ar[k];
    g_relproj2[i] = s;
}

// ---------------- 128x128 register-blocked SGEMM: C = A[M,K] * B[Nn,K]^T ----
// K fixed at 200. Buffers bound inside device code via template selector.
#define BM 128
#define BN 128
#define BK 8
#define SPAD 4

template <int SEL>
__global__ __launch_bounds__(256) void sgemm128() {
    const float* A; const float* B; float* C; int M, Nn;
    if (SEL == 0) { A = g_x;  B = g_BcatA; C = g_projA; M = N_NODES; Nn = 600; }
    else          { A = g_x1; B = g_Bcat2; C = g_proj2; M = N_NODES; Nn = 400; }
    const int K = DIM;

    __shared__ float As[BK][BM + SPAD];
    __shared__ float Bs[BK][BN + SPAD];

    int tid  = threadIdx.x;
    int lrow = tid >> 1;                 // 0..127
    int lk4  = (tid & 1) * 4;            // 0 or 4
    int row0 = blockIdx.y * BM;
    int col0 = blockIdx.x * BN;
    int tx = tid % 16, ty = tid / 16;

    const float* Aptr = A + (size_t)(row0 + lrow) * K + lk4;
    const float* Bptr = B + (size_t)(col0 + lrow) * K + lk4;
    bool aok = (row0 + lrow) < M;
    bool bok = (col0 + lrow) < Nn;

    float4 av = aok ? *(const float4*)Aptr : make_float4(0.f, 0.f, 0.f, 0.f);
    float4 bv = bok ? *(const float4*)Bptr : make_float4(0.f, 0.f, 0.f, 0.f);

    float acc[8][8] = {};

    for (int k0 = 0; k0 < K; k0 += BK) {
        As[lk4 + 0][lrow] = av.x; As[lk4 + 1][lrow] = av.y;
        As[lk4 + 2][lrow] = av.z; As[lk4 + 3][lrow] = av.w;
        Bs[lk4 + 0][lrow] = bv.x; Bs[lk4 + 1][lrow] = bv.y;
        Bs[lk4 + 2][lrow] = bv.z; Bs[lk4 + 3][lrow] = bv.w;
        __syncthreads();

        if (k0 + BK < K) {
            av = aok ? *(const float4*)(Aptr + k0 + BK) : make_float4(0.f, 0.f, 0.f, 0.f);
            bv = bok ? *(const float4*)(Bptr + k0 + BK) : make_float4(0.f, 0.f, 0.f, 0.f);
        }

        #pragma unroll
        for (int k = 0; k < BK; k++) {
            float4 a0 = *(const float4*)&As[k][ty * 8];
            float4 a1 = *(const float4*)&As[k][ty * 8 + 4];
            float4 b0 = *(const float4*)&Bs[k][tx * 8];
            float4 b1 = *(const float4*)&Bs[k][tx * 8 + 4];
            float ar[8] = {a0.x, a0.y, a0.z, a0.w, a1.x, a1.y, a1.z, a1.w};
            float br[8] = {b0.x, b0.y, b0.z, b0.w, b1.x, b1.y, b1.z, b1.w};
            #pragma unroll
            for (int i = 0; i < 8; i++)
                #pragma unroll
                for (int j = 0; j < 8; j++)
                    acc[i][j] += ar[i] * br[j];
        }
        __syncthreads();
    }

    #pragma unroll
    for (int i = 0; i < 8; i++) {
        int gr = row0 + ty * 8 + i;
        if (gr >= M) continue;
        float* crow = C + (size_t)gr * Nn;
        int gc0 = col0 + tx * 8;
        if (gc0 < Nn)
            *(float4*)(crow + gc0) = make_float4(acc[i][0], acc[i][1], acc[i][2], acc[i][3]);
        if (gc0 + 4 < Nn)
            *(float4*)(crow + gc0 + 4) = make_float4(acc[i][4], acc[i][5], acc[i][6], acc[i][7]);
    }
}

// ---------------- edge pass, layer 1 (warp per edge, per head) ----------------
__global__ void edge_pass1(const float* __restrict__ a2_heads) {
    int gw = (blockIdx.x * blockDim.x + threadIdx.x) >> 5;
    int lane = threadIdx.x & 31;
    int h = blockIdx.y;
    if (gw >= E_ALL) return;
    int d = g_dst[gw], s = g_src[gw], ra = g_rA[gw], rb = g_rB[gw];
    const float* pd = g_projA + (size_t)d * 600 + h * 200;
    const float* ps = g_projA + (size_t)s * 600 + h * 200 + 100;
    const float* rp = g_relproj1 + (h * N_RELS + ra) * NHID;
    const float* rp2 = (rb >= 0) ? (g_relproj1 + (h * N_RELS + rb) * NHID) : nullptr;
    const float* a2 = a2_heads + h * NHID;
    float m[4];
    float dot = 0.f;
    #pragma unroll
    for (int t = 0; t < 4; t++) {
        int j = lane + 32 * t;
        float v = 0.f;
        if (j < NHID) {
            v = pd[j] + ps[j] + rp[j];
            if (rp2) v += rp2[j];
            dot += v * a2[j];
        }
        m[t] = v;
    }
    dot = warp_sum(dot);
    float lr = dot > 0.f ? dot : 0.2f * dot;
    float ev = __expf(-lr);
    float* accrow = g_acc1 + ((size_t)h * N_NODES + d) * NHID;
    if (lane == 0) atomicAdd(&g_rowsum1[h * N_NODES + d], ev);
    #pragma unroll
    for (int t = 0; t < 4; t++) {
        int j = lane + 32 * t;
        if (j < NHID) atomicAdd(&accrow[j], ev * m[t]);
    }
}

// ---------------- combine layer-1 heads -> x1 (with elu) ----------------
__global__ void combine1() {
    int i = blockIdx.x * blockDim.x + threadIdx.x;
    if (i >= N_NODES * DIM) return;
    int n = i / DIM, c = i % DIM;
    int h = c / NHID, j = c % NHID;
    float rs = g_rowsum1[h * N_NODES + n];
    rs = (rs == 0.f) ? 1e-12f : rs;
    float v = g_acc1[((size_t)h * N_NODES + n) * NHID + j] / rs;
    g_x1[i] = v > 0.f ? v : (__expf(v) - 1.f);
}

// ---------------- edge pass, layer 2 ----------------
__global__ void edge_pass2(const float* __restrict__ a2_out) {
    int gw = (blockIdx.x * blockDim.x + threadIdx.x) >> 5;
    int lane = threadIdx.x & 31;
    if (gw >= E_ALL) return;
    int d = g_dst[gw], s = g_src[gw], ra = g_rA[gw], rb = g_rB[gw];
    const float* pd = g_proj2 + (size_t)d * 400;
    const float* ps = g_proj2 + (size_t)s * 400 + 200;
    const float* rp = g_relproj2 + ra * DIM;
    const float* rp2 = (rb >= 0) ? (g_relproj2 + rb * DIM) : nullptr;
    float m[7];
    float dot = 0.f;
    #pragma unroll
    for (int t = 0; t < 7; t++) {
        int j = lane + 32 * t;
        float v = 0.f;
        if (j < DIM) {
            v = pd[j] + ps[j] + rp[j];
            if (rp2) v += rp2[j];
            dot += v * a2_out[j];
        }
        m[t] = v;
    }
    dot = warp_sum(dot);
    float lr = dot > 0.f ? dot : 0.2f * dot;
    float ev = __expf(-lr);
    float* accrow = g_acc2 + (size_t)d * DIM;
    if (lane == 0) atomicAdd(&g_rowsum2[d], ev);
    #pragma unroll
    for (int t = 0; t < 7; t++) {
        int j = lane + 32 * t;
        if (j < DIM) atomicAdd(&accrow[j], ev * m[t]);
    }
}

// ---------------- finalize: out_ent = l2norm(entlin + mask*elu(acc2/rs)) ----
__global__ void finalize(float* __restrict__ out) {
    int n = (blockIdx.x * blockDim.x + threadIdx.x) >> 5;
    int lane = threadIdx.x & 31;
    if (n >= N_NODES) return;
    float rs = g_rowsum2[n];
    rs = (rs == 0.f) ? 1e-12f : rs;
    float mk = g_mask[n];
    float v[7];
    float ss = 0.f;
    #pragma unroll
    for (int t = 0; t < 7; t++) {
        int j = lane + 32 * t;
        float val = 0.f;
        if (j < DIM) {
            float hp = g_acc2[(size_t)n * DIM + j] / rs;
            float el = hp > 0.f ? hp : (expf(hp) - 1.f);
            val = g_projA[(size_t)n * 600 + 400 + j] + mk * el;
            ss += val * val;
        }
        v[t] = val;
    }
    ss = warp_sum(ss);
    float sc = 1.f / fmaxf(sqrtf(ss), 1e-12f);
    #pragma unroll
    for (int t = 0; t < 7; t++) {
        int j = lane + 32 * t;
        if (j < DIM) out[(size_t)n * DIM + j] = v[t] * sc;
    }
}

__global__ void copy_tail(float* __restrict__ out) {
    int i = blockIdx.x * blockDim.x + threadIdx.x;
    const size_t base = (size_t)N_NODES * DIM;
    if (i < N_RELS * DIM) out[base + i] = g_outrel[i];
    if (i < N_NODES) out[base + N_RELS * DIM + i] = g_mask[i];
}

// ---------------- launch ----------------
extern "C" void kernel_launch(void* const* d_in, const int* in_sizes, int n_in,
                              void* d_out, int out_size) {
    const float* ent   = (const float*)d_in[0];
    const float* rel   = (const float*)d_in[1];
    const float* W_ent = (const float*)d_in[2];
    const float* W_gat = (const float*)d_in[3];
    const float* a_h   = (const float*)d_in[4];
    const float* a2_h  = (const float*)d_in[5];
    const float* a_o   = (const float*)d_in[6];
    const float* a2_o  = (const float*)d_in[7];
    const int*   batch = (const int*)d_in[8];
    const int*   elist = (const int*)d_in[9];
    const int*   etype = (const int*)d_in[10];
    const int*   nhop  = (const int*)d_in[11];
    float* out = (float*)d_out;
    int n_batch = in_sizes[8];

    zero_all<<<4096, 256>>>();
    prep<<<(E_ALL + 255) / 256, 256>>>(a_h, a_o, W_ent, elist, etype, nhop);
    mask_scatter<<<(n_batch + 255) / 256, 256>>>(batch, n_batch);
    l2norm_entities<<<(N_NODES * 32 + 255) / 256, 256>>>(ent);
    relproj1_k<<<(NHEADS * N_RELS * NHID + 255) / 256, 256>>>(rel, a_h);

    {   // projA = [x@Bcat1^T | x@W_ent]  (N=600)
        dim3 grid((600 + BN - 1) / BN, (N_NODES + BM - 1) / BM);
        sgemm128<0><<<grid, 256>>>();
    }

    {
        dim3 grid((E_ALL + 7) / 8, NHEADS);
        edge_pass1<<<grid, 256>>>(a2_h);
    }
    combine1<<<(N_NODES * DIM + 255) / 256, 256>>>();

    outrel_k<<<(N_RELS * DIM + 255) / 256, 256>>>(rel, W_gat);
    relproj2_k<<<(N_RELS * DIM + 255) / 256, 256>>>(a_o);

    {   // proj2 = x1 @ Bcat2^T  (N=400)
        dim3 grid((400 + BN - 1) / BN, (N_NODES + BM - 1) / BM);
        sgemm128<1><<<grid, 256>>>();
    }

    {
        dim3 grid((E_ALL + 7) / 8, 1);
        edge_pass2<<<grid, 256>>>(a2_o);
    }

    finalize<<<(N_NODES * 32 + 255) / 256, 256>>>(out);
    copy_tail<<<(N_RELS * DIM + 255) / 256, 256>>>(out);
}